// round 4
// baseline (speedup 1.0000x reference)
#include <cuda_runtime.h>
#include <math.h>

// Problem constants: B=16, T=128 -> 2048 graphs; J=75 nodes;
// D_IN=3, HID=64, OUT=256; E=300 edges (derived from in_sizes at launch).
#define NJ    75
#define DIN   3
#define HID   64
#define NOUT  256
#define MAX_E 1024          // setup-kernel capacity for raw edges
#define MAX_T 544           // capacity for CSR entries (E + J = 375 actual)

// Persistent CSR of the normalized adjacency (A = D^-1/2 (Adj + I) D^-1/2),
// built deterministically each launch by setup_csr.
__device__ int   g_csr_src[MAX_T];
__device__ float g_csr_w[MAX_T];
__device__ int   g_csr_off[NJ + 1];

__device__ __forceinline__ float gelu_exact(float v) {
    return 0.5f * v * (1.0f + erff(v * 0.70710678118654752f));
}

__device__ __forceinline__ int clampj(int v) {
    return v < 0 ? 0 : (v >= NJ ? NJ - 1 : v);
}

// ---------------------------------------------------------------------------
// Build CSR (per-dst in-edge lists incl. self-loops) from edge_index (2,E).
// Dtype-agnostic: detects int32 vs int64 storage by checking whether all odd
// 32-bit words of the first 2E words are zero (int64 little-endian of small
// non-negative values). Single block; deterministic fill.
// ---------------------------------------------------------------------------
__global__ void setup_csr(const void* __restrict__ eiv, int E) {
    const int*       e32 = (const int*)eiv;
    const long long* e64 = (const long long*)eiv;

    __shared__ int   s_is64;
    __shared__ int   s_src[MAX_E];
    __shared__ int   s_dst[MAX_E];
    __shared__ int   s_deg[NJ];
    __shared__ float s_dis[NJ];
    __shared__ int   s_off[NJ + 1];

    int t = threadIdx.x;

    if (t == 0) {
        int odd_nonzero = 0;
        for (int i = 1; i < 2 * E; i += 2) odd_nonzero |= (e32[i] != 0);
        s_is64 = !odd_nonzero;
    }
    __syncthreads();
    const int is64 = s_is64;

    for (int i = t; i < E; i += blockDim.x) {
        int sv, dv;
        if (is64) { sv = (int)e64[i]; dv = (int)e64[E + i]; }
        else      { sv = e32[i];      dv = e32[E + i]; }
        s_src[i] = clampj(sv);
        s_dst[i] = clampj(dv);
    }
    for (int j = t; j < NJ; j += blockDim.x) s_deg[j] = 1;  // self loop
    __syncthreads();
    for (int i = t; i < E; i += blockDim.x) atomicAdd(&s_deg[s_dst[i]], 1);
    __syncthreads();
    if (t == 0) {
        int acc = 0;
        for (int j = 0; j < NJ; j++) { s_off[j] = acc; acc += s_deg[j]; }
        s_off[NJ] = acc;
    }
    for (int j = t; j < NJ; j += blockDim.x) s_dis[j] = rsqrtf((float)s_deg[j]);
    __syncthreads();
    if (t < NJ) {
        int p = s_off[t];
        float dj = s_dis[t];
        for (int e = 0; e < E; e++) {
            if (s_dst[e] == t) {
                int se = s_src[e];
                g_csr_src[p] = se;
                g_csr_w[p]   = s_dis[se] * dj;
                p++;
            }
        }
        // self loop last (matches reference's concat order: edges then loops)
        g_csr_src[p] = t;
        g_csr_w[p]   = dj * dj;
    }
    for (int j = t; j <= NJ; j += blockDim.x) g_csr_off[j] = s_off[j];
}

// ---------------------------------------------------------------------------
// Fully fused per-graph GCN:
//   out = gelu( A * gelu( (A*x) W1 + b1 ) * W2 + b2 )
// One CTA per (b,t) graph; 256 threads. All intermediates in SMEM.
// ---------------------------------------------------------------------------
__global__ void __launch_bounds__(256)
gcn_fused(const float* __restrict__ x,
          const float* __restrict__ W1, const float* __restrict__ b1,
          const float* __restrict__ W2, const float* __restrict__ b2,
          float* __restrict__ out, int nTot) {
    // 16B alignment required: several of these are read via float4 (LDS.128).
    __shared__ __align__(16) float s_x  [NJ * DIN];
    __shared__ __align__(16) float s_ax [NJ * DIN];
    __shared__ __align__(16) float s_h1 [NJ * HID];
    __shared__ __align__(16) float s_ah1[NJ * HID];
    __shared__ __align__(16) float s_W1 [DIN * HID];
    __shared__ __align__(16) float s_b1 [HID];
    __shared__ __align__(16) float s_b2 [NOUT];
    __shared__ int   s_off[NJ + 1];
    __shared__ int   s_src[MAX_T];
    __shared__ __align__(16) float s_w[MAX_T];

    const int t = threadIdx.x;
    const int g = blockIdx.x;

    // ---- cooperative loads ----
    const float* xg = x + (size_t)g * (NJ * DIN);
    for (int i = t; i < NJ * DIN; i += 256) s_x[i] = xg[i];
    for (int i = t; i < DIN * HID; i += 256) s_W1[i] = W1[i];
    if (t < HID) s_b1[t] = b1[t];
    s_b2[t] = b2[t];
    for (int i = t; i <= NJ; i += 256) s_off[i] = g_csr_off[i];
    for (int i = t; i < nTot; i += 256) { s_src[i] = g_csr_src[i]; s_w[i] = g_csr_w[i]; }
    __syncthreads();

    // ---- phase 1: ax = A * x  (J*3 = 225 outputs) ----
    for (int idx = t; idx < NJ * DIN; idx += 256) {
        int j = idx / DIN, d = idx - j * DIN;
        float acc = 0.f;
        int e0 = s_off[j], e1 = s_off[j + 1];
        for (int e = e0; e < e1; e++) acc += s_w[e] * s_x[s_src[e] * DIN + d];
        s_ax[idx] = acc;
    }
    __syncthreads();

    // ---- phase 2: h1 = gelu(ax @ W1 + b1)  (J*64 outputs) ----
    for (int idx = t; idx < NJ * HID; idx += 256) {
        int j = idx >> 6, k = idx & 63;
        float a0 = s_ax[j * DIN + 0];
        float a1 = s_ax[j * DIN + 1];
        float a2 = s_ax[j * DIN + 2];
        float v = fmaf(a0, s_W1[k],
                  fmaf(a1, s_W1[HID + k],
                  fmaf(a2, s_W1[2 * HID + k], s_b1[k])));
        s_h1[idx] = gelu_exact(v);
    }
    __syncthreads();

    // ---- phase 3: ah1 = A * h1 ----
    for (int idx = t; idx < NJ * HID; idx += 256) {
        int j = idx >> 6, k = idx & 63;
        float acc = 0.f;
        int e0 = s_off[j], e1 = s_off[j + 1];
        for (int e = e0; e < e1; e++) acc += s_w[e] * s_h1[(s_src[e] << 6) + k];
        s_ah1[idx] = acc;
    }
    __syncthreads();

    // ---- phase 4: out = gelu(ah1 @ W2 + b2), write coalesced ----
    // Thread t owns output channel c = t; W2 column in registers.
    float w2c[HID];
#pragma unroll
    for (int k = 0; k < HID; k++) w2c[k] = W2[k * NOUT + t];
    const float bc = s_b2[t];
    float* og = out + (size_t)g * (NJ * NOUT) + t;

    for (int j = 0; j < NJ; j++) {
        const float4* row = (const float4*)(s_ah1 + j * HID);  // 256B-stride rows, 16B-aligned base
        float acc = bc;
#pragma unroll
        for (int k4 = 0; k4 < HID / 4; k4++) {
            float4 v = row[k4];  // broadcast LDS.128
            acc = fmaf(v.x, w2c[4 * k4 + 0], acc);
            acc = fmaf(v.y, w2c[4 * k4 + 1], acc);
            acc = fmaf(v.z, w2c[4 * k4 + 2], acc);
            acc = fmaf(v.w, w2c[4 * k4 + 3], acc);
        }
        og[(size_t)j * NOUT] = gelu_exact(acc);
    }
}

// ---------------------------------------------------------------------------
extern "C" void kernel_launch(void* const* d_in, const int* in_sizes, int n_in,
                              void* d_out, int out_size) {
    const float* x  = (const float*)d_in[0];
    const void*  ei = d_in[1];                     // int32 or int64 (2, E)
    const float* W1 = (const float*)d_in[2];
    const float* b1 = (const float*)d_in[3];
    const float* W2 = (const float*)d_in[4];
    const float* b2 = (const float*)d_in[5];
    float* out = (float*)d_out;

    const int E  = in_sizes[1] / 2;                // 300
    const int nG = in_sizes[0] / (NJ * DIN);       // 2048 graphs
    const int nTot = E + NJ;                       // CSR entries

    setup_csr<<<1, 128>>>(ei, E);
    gcn_fused<<<nG, 256>>>(x, W1, b1, W2, b2, out, nTot);
}